// round 1
// baseline (speedup 1.0000x reference)
#include <cuda_runtime.h>
#include <cstdint>

#define DIMS 2048
#define NCLS 4000
#define NROWS 32768
#define NTHR 256
#define MOM 0.9f
#define EPS 1e-12f

// Scratch: segment sums and counts (graph-safe __device__ globals, no allocs)
__device__ float g_seg[2][NCLS][DIMS];   // 65.5 MB
__device__ float g_cnt[2][NCLS];

__device__ __forceinline__ float blockReduceSum(float v, float* sh) {
    int lane = threadIdx.x & 31;
    int w = threadIdx.x >> 5;
    #pragma unroll
    for (int o = 16; o > 0; o >>= 1) v += __shfl_xor_sync(0xffffffffu, v, o);
    if (lane == 0) sh[w] = v;
    __syncthreads();
    if (w == 0) {
        float x = (lane < (NTHR >> 5)) ? sh[lane] : 0.f;
        #pragma unroll
        for (int o = 4; o > 0; o >>= 1) x += __shfl_xor_sync(0xffffffffu, x, o);
        if (lane == 0) sh[0] = x;
    }
    __syncthreads();
    float r = sh[0];
    __syncthreads();   // make sh reusable by a following reduction
    return r;
}

__device__ __forceinline__ void red_add_v4(float* addr, float4 v) {
    asm volatile("red.global.add.v4.f32 [%0], {%1,%2,%3,%4};"
                 :: "l"(addr), "f"(v.x), "f"(v.y), "f"(v.z), "f"(v.w)
                 : "memory");
}

__global__ void zero_scratch() {
    float4* p = reinterpret_cast<float4*>(&g_seg[0][0][0]);
    const size_t n4 = (size_t)2 * NCLS * DIMS / 4;
    for (size_t i = (size_t)blockIdx.x * blockDim.x + threadIdx.x; i < n4;
         i += (size_t)gridDim.x * blockDim.x)
        p[i] = make_float4(0.f, 0.f, 0.f, 0.f);
    float* c = &g_cnt[0][0];
    for (size_t i = (size_t)blockIdx.x * blockDim.x + threadIdx.x; i < (size_t)2 * NCLS;
         i += (size_t)gridDim.x * blockDim.x)
        c[i] = 0.f;
}

// One block per feature row. Normalize row, RED-scatter into g_seg[modality][id].
__global__ __launch_bounds__(NTHR) void norm_scatter(
    const float* __restrict__ fv, const float* __restrict__ fr,
    const int* __restrict__ idv, const int* __restrict__ idr)
{
    __shared__ float sh[32];
    const int m = blockIdx.y;
    const int row = blockIdx.x;
    const float* f = (m == 0 ? fv : fr) + (size_t)row * DIMS;
    const int id = (m == 0 ? idv : idr)[row];
    const int t = threadIdx.x;

    const float4* f4 = reinterpret_cast<const float4*>(f);
    float4 a = __ldg(&f4[t]);
    float4 b = __ldg(&f4[t + NTHR]);

    float ss = a.x*a.x + a.y*a.y + a.z*a.z + a.w*a.w
             + b.x*b.x + b.y*b.y + b.z*b.z + b.w*b.w;
    ss = blockReduceSum(ss, sh);
    const float scale = 1.f / fmaxf(sqrtf(ss), EPS);

    a.x *= scale; a.y *= scale; a.z *= scale; a.w *= scale;
    b.x *= scale; b.y *= scale; b.z *= scale; b.w *= scale;

    float* dst = &g_seg[m][id][0];
    red_add_v4(dst + 4 * t, a);
    red_add_v4(dst + 4 * (t + NTHR), b);
    if (t == 0) atomicAdd(&g_cnt[m][id], 1.f);
}

// One block per (modality, class): mean -> l2norm -> blend -> l2norm -> select.
__global__ __launch_bounds__(NTHR) void finalize(
    const float* __restrict__ vism, const float* __restrict__ irm,
    float* __restrict__ out)
{
    __shared__ float sh[32];
    const int m = blockIdx.y;
    const int c = blockIdx.x;
    const int t = threadIdx.x;

    const float* mem = (m == 0 ? vism : irm) + (size_t)c * DIMS;
    const float cnt = g_cnt[m][c];

    const float4* s4 = reinterpret_cast<const float4*>(&g_seg[m][c][0]);
    const float4* m4 = reinterpret_cast<const float4*>(mem);
    float4 s0 = s4[t], s1 = s4[t + NTHR];
    float4 w0 = __ldg(&m4[t]), w1 = __ldg(&m4[t + NTHR]);

    // mean = seg / max(cnt, 1)
    const float invc = 1.f / fmaxf(cnt, 1.f);
    s0.x *= invc; s0.y *= invc; s0.z *= invc; s0.w *= invc;
    s1.x *= invc; s1.y *= invc; s1.z *= invc; s1.w *= invc;

    float ssm = s0.x*s0.x + s0.y*s0.y + s0.z*s0.z + s0.w*s0.w
              + s1.x*s1.x + s1.y*s1.y + s1.z*s1.z + s1.w*s1.w;
    ssm = blockReduceSum(ssm, sh);
    const float inm = 1.f / fmaxf(sqrtf(ssm), EPS);

    // t = MOM*mem + (1-MOM)*mean_n
    float4 t0, t1;
    t0.x = MOM * w0.x + (1.f - MOM) * (s0.x * inm);
    t0.y = MOM * w0.y + (1.f - MOM) * (s0.y * inm);
    t0.z = MOM * w0.z + (1.f - MOM) * (s0.z * inm);
    t0.w = MOM * w0.w + (1.f - MOM) * (s0.w * inm);
    t1.x = MOM * w1.x + (1.f - MOM) * (s1.x * inm);
    t1.y = MOM * w1.y + (1.f - MOM) * (s1.y * inm);
    t1.z = MOM * w1.z + (1.f - MOM) * (s1.z * inm);
    t1.w = MOM * w1.w + (1.f - MOM) * (s1.w * inm);

    float sst = t0.x*t0.x + t0.y*t0.y + t0.z*t0.z + t0.w*t0.w
              + t1.x*t1.x + t1.y*t1.y + t1.z*t1.z + t1.w*t1.w;
    sst = blockReduceSum(sst, sh);
    const float int_ = 1.f / fmaxf(sqrtf(sst), EPS);

    const bool present = (cnt > 0.f);
    float4 o0, o1;
    o0.x = present ? t0.x * int_ : w0.x;
    o0.y = present ? t0.y * int_ : w0.y;
    o0.z = present ? t0.z * int_ : w0.z;
    o0.w = present ? t0.w * int_ : w0.w;
    o1.x = present ? t1.x * int_ : w1.x;
    o1.y = present ? t1.y * int_ : w1.y;
    o1.z = present ? t1.z * int_ : w1.z;
    o1.w = present ? t1.w * int_ : w1.w;

    float4* o4 = reinterpret_cast<float4*>(out + (size_t)m * NCLS * DIMS + (size_t)c * DIMS);
    o4[t] = o0;
    o4[t + NTHR] = o1;
}

extern "C" void kernel_launch(void* const* d_in, const int* in_sizes, int n_in,
                              void* d_out, int out_size) {
    const float* fv   = (const float*)d_in[0];
    const float* fr   = (const float*)d_in[1];
    const int*   idv  = (const int*)d_in[2];
    const int*   idr  = (const int*)d_in[3];
    const float* vism = (const float*)d_in[4];
    const float* irm  = (const float*)d_in[5];
    float* out = (float*)d_out;

    zero_scratch<<<2048, NTHR>>>();
    norm_scatter<<<dim3(NROWS, 2), NTHR>>>(fv, fr, idv, idr);
    finalize<<<dim3(NCLS, 2), NTHR>>>(vism, irm, out);
}